// round 1
// baseline (speedup 1.0000x reference)
#include <cuda_runtime.h>

#define GRIDX 128
#define NTH   256
#define BB    128
#define SS    512
#define II    128
#define HH    512

// persistent device state (no allocations allowed)
static __device__ float g_h0[2][BB * HH];
static __device__ float g_h1[2][BB * HH];
static __device__ float g_dec_in[BB * II];
static __device__ unsigned g_arrive = 0;
static __device__ unsigned g_release = 0;

__device__ __forceinline__ float sigf(float x) { return 1.0f / (1.0f + __expf(-x)); }
// robust tanh via expf: saturates correctly for large |x|
__device__ __forceinline__ float tanhfast(float x) { return 1.0f - 2.0f / (__expf(2.0f * x) + 1.0f); }

// software grid barrier: 128 co-resident CTAs (1/SM guaranteed by 131KB smem)
__device__ __forceinline__ void grid_sync(unsigned base, unsigned target)
{
    __syncthreads();
    if (threadIdx.x == 0) {
        __threadfence();                         // release (flushes, orders prior writes)
        unsigned arrived = atomicAdd(&g_arrive, 1u);
        if (arrived == GRIDX - 1u) {
            g_arrive = 0u;
            __threadfence();
            atomicAdd(&g_release, 1u);
        } else {
            volatile unsigned* rel = &g_release;
            while ((*rel - base) < target) { __nanosleep(64); }
        }
        __threadfence();                         // acquire (CCTL.IVALL -> L1 invalidate)
    }
    __syncthreads();
}

// Load one layer's weights into SMEM as Wc[k][16], column c = j*4+gt maps to
// global gate-row R = gt*H + u0 + j.  Acts layout during GEMM: concat(inA, h).
__device__ void load_layer_weights(float* Wc, float* bias, int lenA,
                                   const float* __restrict__ W_ih,
                                   const float* __restrict__ W_hh,
                                   const float* __restrict__ b_ih,
                                   const float* __restrict__ b_hh, int u0)
{
    const int tid = threadIdx.x;
    const int K = lenA + HH;
    for (int idx = tid; idx < K * 16; idx += NTH) {
        int k  = idx >> 4;
        int c  = idx & 15;
        int j  = c >> 2;
        int gt = c & 3;
        int R  = gt * HH + u0 + j;
        float v = (k < lenA) ? W_ih[R * lenA + k] : W_hh[R * HH + (k - lenA)];
        Wc[idx] = v;
    }
    if (tid < 16) {
        int j = tid >> 2, gt = tid & 3;
        int R = gt * HH + u0 + j;
        bias[tid] = b_ih[R] + b_hh[R];
    }
}

// One LSTM layer step for this CTA's 4 units over all 128 batches.
// gates[b, 16] = concat(srcA[b,:lenA], srcB[b,:512]) @ Wc + bias, then cell update.
// Threads: kc = tid>>7 (split-K half), gg = (tid>>5)&3 (unit), bg = tid&31 (4 batches).
__device__ void lstm_layer(const float* __restrict__ srcA, int strideA, int lenA,
                           const float* __restrict__ srcB,
                           const float* __restrict__ Wc, const float* __restrict__ bias,
                           float* __restrict__ A_s, float* __restrict__ red,
                           float* __restrict__ hout, float* c_state, int u0)
{
    const int tid = threadIdx.x;
    const int kc  = tid >> 7;
    const int sub = tid & 127;
    const int gg  = sub >> 5;
    const int bg  = sub & 31;
    const int K   = lenA + HH;

    float acc[4][4];
#pragma unroll
    for (int bi = 0; bi < 4; bi++)
#pragma unroll
        for (int gt = 0; gt < 4; gt++)
            acc[bi][gt] = (kc == 0) ? bias[gg * 4 + gt] : 0.0f;

    const int b_st   = tid >> 1;         // staging: batch this thread loads
    const int kk0_st = (tid & 1) * 16;   // staging: k-offset within tile

    for (int k0 = 0; k0 < K; k0 += 32) {
        __syncthreads();
        // stage 32 x 128 act tile (A_s[kk][b], padded stride 132)
        {
            int kglob = k0 + kk0_st;
            const float* src = (kglob < lenA) ? (srcA + (size_t)b_st * strideA + kglob)
                                              : (srcB + b_st * HH + (kglob - lenA));
#pragma unroll
            for (int q = 0; q < 4; q++) {
                float4 v = *(const float4*)(src + q * 4);
                int kk = kk0_st + q * 4;
                A_s[(kk + 0) * 132 + b_st] = v.x;
                A_s[(kk + 1) * 132 + b_st] = v.y;
                A_s[(kk + 2) * 132 + b_st] = v.z;
                A_s[(kk + 3) * 132 + b_st] = v.w;
            }
        }
        __syncthreads();
        const float* Wk = Wc + k0 * 16;
#pragma unroll
        for (int q = 0; q < 16; q++) {
            int kk = (kc << 4) + q;
            float4 a = *(const float4*)&A_s[kk * 132 + (bg << 2)];
            float4 w = *(const float4*)&Wk[kk * 16 + (gg << 2)];
            acc[0][0] += a.x * w.x; acc[0][1] += a.x * w.y; acc[0][2] += a.x * w.z; acc[0][3] += a.x * w.w;
            acc[1][0] += a.y * w.x; acc[1][1] += a.y * w.y; acc[1][2] += a.y * w.z; acc[1][3] += a.y * w.w;
            acc[2][0] += a.z * w.x; acc[2][1] += a.z * w.y; acc[2][2] += a.z * w.z; acc[2][3] += a.z * w.w;
            acc[3][0] += a.w * w.x; acc[3][1] += a.w * w.y; acc[3][2] += a.w * w.z; acc[3][3] += a.w * w.w;
        }
    }
    __syncthreads();
    if (kc == 1) {
#pragma unroll
        for (int bi = 0; bi < 4; bi++)
#pragma unroll
            for (int gt = 0; gt < 4; gt++)
                red[sub * 17 + bi * 4 + gt] = acc[bi][gt];
    }
    __syncthreads();
    if (kc == 0) {
        const int u = u0 + gg;
#pragma unroll
        for (int bi = 0; bi < 4; bi++) {
            float iv = acc[bi][0] + red[sub * 17 + bi * 4 + 0];
            float fv = acc[bi][1] + red[sub * 17 + bi * 4 + 1];
            float gv = acc[bi][2] + red[sub * 17 + bi * 4 + 2];
            float ov = acc[bi][3] + red[sub * 17 + bi * 4 + 3];
            float c = sigf(fv) * c_state[bi] + sigf(iv) * tanhfast(gv);
            c_state[bi] = c;
            int b = (bg << 2) + bi;
            hout[b * HH + u] = sigf(ov) * tanhfast(c);
        }
    }
}

// Decoder output column: pred[b, icol] = h1[b,:] . wlin_s[:]
__device__ void pred_linear(const float* __restrict__ h1,
                            const float* __restrict__ wlin_s,
                            float* __restrict__ A_s, float* __restrict__ red,
                            int t, float* __restrict__ outp, int icol)
{
    const int tid = threadIdx.x;
    const int kc  = tid >> 7;
    const int sub = tid & 127;
    float acc = 0.0f;
    const int b_st   = tid >> 1;
    const int kk0_st = (tid & 1) * 16;

    for (int k0 = 0; k0 < HH; k0 += 32) {
        __syncthreads();
        {
            const float* src = h1 + b_st * HH + k0 + kk0_st;
#pragma unroll
            for (int q = 0; q < 4; q++) {
                float4 v = *(const float4*)(src + q * 4);
                int kk = kk0_st + q * 4;
                A_s[(kk + 0) * 132 + b_st] = v.x;
                A_s[(kk + 1) * 132 + b_st] = v.y;
                A_s[(kk + 2) * 132 + b_st] = v.z;
                A_s[(kk + 3) * 132 + b_st] = v.w;
            }
        }
        __syncthreads();
#pragma unroll
        for (int q = 0; q < 16; q++) {
            int kk = (kc << 4) + q;
            acc += A_s[kk * 132 + sub] * wlin_s[k0 + kk];
        }
    }
    __syncthreads();
    if (kc == 1) red[sub] = acc;
    __syncthreads();
    if (kc == 0) {
        float p = acc + red[sub];
        outp[((size_t)sub * SS + t) * II + icol] = p;
        g_dec_in[sub * II + icol] = p;
    }
}

__global__ void __launch_bounds__(NTH, 1)
lstm_ae_kernel(const float* __restrict__ x,
               const float* Wih_en0, const float* Whh_en0, const float* bih_en0, const float* bhh_en0,
               const float* Wih_en1, const float* Whh_en1, const float* bih_en1, const float* bhh_en1,
               const float* Wih_de0, const float* Whh_de0, const float* bih_de0, const float* bhh_de0,
               const float* Wih_de1, const float* Whh_de1, const float* bih_de1, const float* bhh_de1,
               const float* Wlin,
               float* __restrict__ out)
{
    extern __shared__ float sm[];
    float* Wc1    = sm;                  // 16384 floats  (K=1024 layer)
    float* Wc0    = Wc1 + 16384;         // 10240 floats  (K=640 layer)
    float* A_s    = Wc0 + 10240;         // 32*132 = 4224
    float* red    = A_s + 4224;          // 128*17 = 2176
    float* wlin_s = red + 2176;          // 512
    float* bias0  = wlin_s + 512;        // 16
    float* bias1  = bias0 + 16;          // 16

    const int tid = threadIdx.x;
    const int u0  = blockIdx.x * 4;

    __shared__ unsigned s_base;
    if (tid == 0) s_base = atomicAdd(&g_release, 0u);   // snapshot before any barrier

    // zero initial states + decoder feedback input
    {
        int g = blockIdx.x * NTH + tid;
        for (int i = g; i < BB * HH; i += GRIDX * NTH) { g_h0[0][i] = 0.0f; g_h1[0][i] = 0.0f; }
        for (int i = g; i < BB * II; i += GRIDX * NTH) g_dec_in[i] = 0.0f;
    }

    // encoder weights -> SMEM (once)
    load_layer_weights(Wc0, bias0, II, Wih_en0, Whh_en0, bih_en0, bhh_en0, u0);
    load_layer_weights(Wc1, bias1, HH, Wih_en1, Whh_en1, bih_en1, bhh_en1, u0);
    __syncthreads();

    unsigned base = s_base;
    unsigned nsync = 0;
    grid_sync(base, ++nsync);   // zero-init + everyone ready

    float c0[4] = {0.f, 0.f, 0.f, 0.f};
    float c1[4] = {0.f, 0.f, 0.f, 0.f};

    int p = 0;
    // ---- encoder ----
    for (int t = 0; t < SS; t++) {
        lstm_layer(x + (size_t)t * II, SS * II, II, g_h0[p], Wc0, bias0, A_s, red, g_h0[p ^ 1], c0, u0);
        grid_sync(base, ++nsync);
        lstm_layer(g_h0[p ^ 1], HH, HH, g_h1[p], Wc1, bias1, A_s, red, g_h1[p ^ 1], c1, u0);
        grid_sync(base, ++nsync);
        p ^= 1;
    }

    // ---- swap to decoder weights ----
    load_layer_weights(Wc0, bias0, II, Wih_de0, Whh_de0, bih_de0, bhh_de0, u0);
    load_layer_weights(Wc1, bias1, HH, Wih_de1, Whh_de1, bih_de1, bhh_de1, u0);
    for (int idx = tid; idx < HH; idx += NTH) wlin_s[idx] = Wlin[blockIdx.x * HH + idx];
    __syncthreads();

    // ---- decoder (closed loop) ----
    for (int t = 0; t < SS; t++) {
        lstm_layer(g_dec_in, II, II, g_h0[p], Wc0, bias0, A_s, red, g_h0[p ^ 1], c0, u0);
        grid_sync(base, ++nsync);
        lstm_layer(g_h0[p ^ 1], HH, HH, g_h1[p], Wc1, bias1, A_s, red, g_h1[p ^ 1], c1, u0);
        grid_sync(base, ++nsync);
        pred_linear(g_h1[p ^ 1], wlin_s, A_s, red, t, out, blockIdx.x);
        grid_sync(base, ++nsync);
        p ^= 1;
    }
}

extern "C" void kernel_launch(void* const* d_in, const int* in_sizes, int n_in,
                              void* d_out, int out_size)
{
    const float* p[18];
    for (int i = 0; i < 18; i++) p[i] = (const float*)d_in[i];

    const size_t shmem = (16384 + 10240 + 4224 + 2176 + 512 + 16 + 16) * sizeof(float); // 134272 B
    cudaFuncSetAttribute(lstm_ae_kernel, cudaFuncAttributeMaxDynamicSharedMemorySize, (int)shmem);

    lstm_ae_kernel<<<GRIDX, NTH, shmem>>>(
        p[0],
        p[1], p[2], p[3], p[4],
        p[5], p[6], p[7], p[8],
        p[9], p[10], p[11], p[12],
        p[13], p[14], p[15], p[16],
        p[17],
        (float*)d_out);
}

// round 3
// speedup vs baseline: 1.2718x; 1.2718x over previous
#include <cuda_runtime.h>
#include <cstdint>

#define GRIDX 128
#define NTH   256
#define BB    128
#define SS    512
#define II    128
#define HH    512
#define TK    64              // k-rows per staged tile
#define TILEF (TK*BB)         // floats per tile (8192)

// persistent device state (no allocations allowed)
static __device__ __align__(16) float g_h0T[2][HH*BB];
static __device__ __align__(16) float g_h1T[2][HH*BB];
static __device__ __align__(16) float g_decT[II*BB];
static __device__ __align__(16) float g_xT[SS*II*BB];
static __device__ unsigned g_arrive = 0;
static __device__ unsigned g_release = 0;

__device__ __forceinline__ float sigf(float x){ return 1.0f/(1.0f+__expf(-x)); }
__device__ __forceinline__ float tanhf_(float x){ return 1.0f - 2.0f/(__expf(2.0f*x)+1.0f); }

// ---- packed f32x2 helpers (sm_103a dual-rate fp32) ----
#define PACK2(d,lo,hi) asm("mov.b64 %0,{%1,%2};" : "=l"(d) : "f"(lo),"f"(hi))
#define UNPK2(lo,hi,s) asm("mov.b64 {%0,%1},%2;" : "=f"(lo),"=f"(hi) : "l"(s))
#define FMA2(d,a,b)    asm("fma.rn.f32x2 %0,%1,%2,%0;" : "+l"(d) : "l"(a),"l"(b))
#define ADD2(d,a)      asm("add.rn.f32x2 %0,%0,%1;" : "+l"(d) : "l"(a))
#define LDS_V2B64(a0,a1,addr) asm volatile("ld.shared.v2.b64 {%0,%1},[%2];" : "=l"(a0),"=l"(a1) : "r"(addr))

// ---- cp.async ----
#define CPA16(d,s) asm volatile("cp.async.cg.shared.global [%0],[%1],16;" :: "r"(d),"l"(s))
#define CPC()      asm volatile("cp.async.commit_group;")
#define CPW(n)     asm volatile("cp.async.wait_group %0;" :: "n"(n))

// software grid barrier: 128 co-resident CTAs (1/SM guaranteed by ~200KB smem)
__device__ __forceinline__ void grid_sync(unsigned base, unsigned target)
{
    __syncthreads();
    if (threadIdx.x == 0) {
        __threadfence();
        unsigned arrived = atomicAdd(&g_arrive, 1u);
        if (arrived == GRIDX - 1u) {
            g_arrive = 0u;
            __threadfence();
            atomicAdd(&g_release, 1u);
        } else {
            volatile unsigned* rel = &g_release;
            while ((*rel - base) < target) { __nanosleep(32); }
        }
        __threadfence();
    }
    __syncthreads();
}

// Weights -> SMEM as Wc[k][16]; col c = unit*4 + gate, global row R = gate*H + u0 + unit.
__device__ void load_layer_weights(float* Wc, float* bias, int lenA,
                                   const float* __restrict__ W_ih,
                                   const float* __restrict__ W_hh,
                                   const float* __restrict__ b_ih,
                                   const float* __restrict__ b_hh, int u0)
{
    const int tid = threadIdx.x;
    const int K = lenA + HH;
    for (int idx = tid; idx < K * 16; idx += NTH) {
        int k  = idx >> 4;
        int c  = idx & 15;
        int j  = c >> 2;
        int gt = c & 3;
        int R  = gt * HH + u0 + j;
        float v = (k < lenA) ? W_ih[R * lenA + k] : W_hh[R * HH + (k - lenA)];
        Wc[idx] = v;
    }
    if (tid < 16) {
        int j = tid >> 2, gt = tid & 3;
        int R = gt * HH + u0 + j;
        bias[tid] = b_ih[R] + b_hh[R];
    }
}

// stage one contiguous 64x128 fp32 tile (32KB) via cp.async
__device__ __forceinline__ void stage_tile(uint32_t dstS, const float* __restrict__ src)
{
    const int tid = threadIdx.x;
#pragma unroll
    for (int j = 0; j < 8; j++) {
        int idx = tid + j * NTH;               // 0..2047 chunks of 16B
        CPA16(dstS + idx * 16, src + idx * 4);
    }
}

// One LSTM layer step for this CTA's 4 units over all 128 batches.
// acts = concat(srcA rows [tilesA*64], srcB rows [tilesB*64]), both [k][128] contiguous.
// Threads: kc = tid>>6 (split-K-4), gg = unit (0..3), bg = batch-group (8 batches).
__device__ void lstm_step(const float* __restrict__ srcA, int tilesA,
                          const float* __restrict__ srcB, int tilesB,
                          const float* __restrict__ Wc, const float* __restrict__ bias_s,
                          float* __restrict__ A_s, float* __restrict__ red,
                          float* __restrict__ hrow_base, float* c_st)
{
    const int tid = threadIdx.x;
    const int kc = tid >> 6, r = tid & 63, gg = r >> 4, bg = r & 15;
    const int nT = tilesA + tilesB;

    unsigned long long acc[4][4];
    if (kc == 0) {
#pragma unroll
        for (int g = 0; g < 4; g++) {
            float b = bias_s[gg * 4 + g];
            unsigned long long bb; PACK2(bb, b, b);
#pragma unroll
            for (int bp = 0; bp < 4; bp++) acc[bp][g] = bb;
        }
    } else {
        unsigned long long z; PACK2(z, 0.0f, 0.0f);
#pragma unroll
        for (int bp = 0; bp < 4; bp++)
#pragma unroll
            for (int g = 0; g < 4; g++) acc[bp][g] = z;
    }

    uint32_t asBase = (uint32_t)__cvta_generic_to_shared(A_s);
    uint32_t aoff   = (uint32_t)((kc * 16 * BB + bg * 8) * 4);

    // prologue: stage tile 0
    stage_tile(asBase, (0 < tilesA) ? srcA : srcB);
    CPC();

    for (int t = 0; t < nT; t++) {
        if (t + 1 < nT) {
            const float* sn = (t + 1 < tilesA) ? srcA + (t + 1) * TILEF
                                               : srcB + (t + 1 - tilesA) * TILEF;
            stage_tile(asBase + ((t + 1) & 1) * TILEF * 4, sn);
            CPC();
            CPW(1);
        } else {
            CPW(0);
        }
        __syncthreads();

        uint32_t aT = asBase + (t & 1) * TILEF * 4 + aoff;
        const float* Wk = Wc + t * TK * 16;
#pragma unroll
        for (int q = 0; q < 16; q++) {
            unsigned long long a0, a1, a2, a3;
            uint32_t ad = aT + q * (BB * 4);
            LDS_V2B64(a0, a1, ad);
            LDS_V2B64(a2, a3, ad + 16);   // FIX: batches 4..7 are +16B, not +32B
            float4 w = *(const float4*)&Wk[(kc * 16 + q) * 16 + gg * 4];
            unsigned long long w0, w1, w2, w3;
            PACK2(w0, w.x, w.x); PACK2(w1, w.y, w.y);
            PACK2(w2, w.z, w.z); PACK2(w3, w.w, w.w);
            FMA2(acc[0][0], a0, w0); FMA2(acc[0][1], a0, w1); FMA2(acc[0][2], a0, w2); FMA2(acc[0][3], a0, w3);
            FMA2(acc[1][0], a1, w0); FMA2(acc[1][1], a1, w1); FMA2(acc[1][2], a1, w2); FMA2(acc[1][3], a1, w3);
            FMA2(acc[2][0], a2, w0); FMA2(acc[2][1], a2, w1); FMA2(acc[2][2], a2, w2); FMA2(acc[2][3], a2, w3);
            FMA2(acc[3][0], a3, w0); FMA2(acc[3][1], a3, w1); FMA2(acc[3][2], a3, w2); FMA2(acc[3][3], a3, w3);
        }
        __syncthreads();   // protect buffer before next-iteration prefetch overwrites it
    }

    // split-K reduction (kc 1..3 -> smem, kc0 accumulates)
    unsigned long long* red64 = (unsigned long long*)red;
    if (kc) {
        int base = ((kc - 1) * 64 + r) * 18;
#pragma unroll
        for (int bp = 0; bp < 4; bp++)
#pragma unroll
            for (int g = 0; g < 4; g++)
                red64[base + bp * 4 + g] = acc[bp][g];
    }
    __syncthreads();
    if (kc == 0) {
#pragma unroll
        for (int j = 0; j < 3; j++) {
            int base = (j * 64 + r) * 18;
#pragma unroll
            for (int bp = 0; bp < 4; bp++)
#pragma unroll
                for (int g = 0; g < 4; g++) {
                    unsigned long long v = red64[base + bp * 4 + g];
                    ADD2(acc[bp][g], v);
                }
        }
        float hv[8];
#pragma unroll
        for (int bp = 0; bp < 4; bp++) {
            float i0, i1, f0, f1, gv0, gv1, o0, o1;
            UNPK2(i0, i1, acc[bp][0]);
            UNPK2(f0, f1, acc[bp][1]);
            UNPK2(gv0, gv1, acc[bp][2]);
            UNPK2(o0, o1, acc[bp][3]);
            float c0n = sigf(f0) * c_st[bp * 2]     + sigf(i0) * tanhf_(gv0);
            float c1n = sigf(f1) * c_st[bp * 2 + 1] + sigf(i1) * tanhf_(gv1);
            c_st[bp * 2]     = c0n;
            c_st[bp * 2 + 1] = c1n;
            hv[bp * 2]     = sigf(o0) * tanhf_(c0n);
            hv[bp * 2 + 1] = sigf(o1) * tanhf_(c1n);
        }
        float* hp = hrow_base + gg * BB + bg * 8;
        *(float4*)hp       = make_float4(hv[0], hv[1], hv[2], hv[3]);
        *(float4*)(hp + 4) = make_float4(hv[4], hv[5], hv[6], hv[7]);
    }
    __syncthreads();
}

// pred[b, icol] = h1[b,:] . wlin (h1 stored transposed [u][b])
__device__ void pred_step(const float* __restrict__ h1T, const float* __restrict__ wlin_s,
                          float* __restrict__ A_s, float* __restrict__ red,
                          int t, float* __restrict__ out, int icol)
{
    const int tid = threadIdx.x;
    const int half = tid >> 7, b = tid & 127;
    uint32_t asBase = (uint32_t)__cvta_generic_to_shared(A_s);
    float acc = 0.0f;

    stage_tile(asBase, h1T);
    CPC();
    for (int tt = 0; tt < 8; tt++) {
        if (tt + 1 < 8) {
            stage_tile(asBase + ((tt + 1) & 1) * TILEF * 4, h1T + (tt + 1) * TILEF);
            CPC();
            CPW(1);
        } else {
            CPW(0);
        }
        __syncthreads();
        const float* As = A_s + (tt & 1) * TILEF + half * 32 * BB + b;
        const float* wl = wlin_s + tt * TK + half * 32;
#pragma unroll
        for (int q = 0; q < 32; q++)
            acc += As[q * BB] * wl[q];
        __syncthreads();
    }
    if (half) red[b] = acc;
    __syncthreads();
    if (!half) {
        float p = acc + red[b];
        out[((size_t)b * SS + t) * II + icol] = p;
        g_decT[icol * BB + b] = p;
    }
    __syncthreads();
}

// x[b][t][i] -> xT[t][i][b]
__global__ void transpose_x(const float* __restrict__ x)
{
    __shared__ float tile[32][33];
    int t = blockIdx.x;
    int i0 = blockIdx.y * 32, b0 = blockIdx.z * 32;
    int tx = threadIdx.x, ty = threadIdx.y;
#pragma unroll
    for (int j = 0; j < 32; j += 8)
        tile[ty + j][tx] = x[((size_t)(b0 + ty + j) * SS + t) * II + i0 + tx];
    __syncthreads();
#pragma unroll
    for (int j = 0; j < 32; j += 8)
        g_xT[((size_t)t * II + i0 + ty + j) * BB + b0 + tx] = tile[tx][ty + j];
}

__global__ void __launch_bounds__(NTH, 1)
lstm_ae_kernel(const float* Wih_en0, const float* Whh_en0, const float* bih_en0, const float* bhh_en0,
               const float* Wih_en1, const float* Whh_en1, const float* bih_en1, const float* bhh_en1,
               const float* Wih_de0, const float* Whh_de0, const float* bih_de0, const float* bhh_de0,
               const float* Wih_de1, const float* Whh_de1, const float* bih_de1, const float* bhh_de1,
               const float* Wlin,
               float* __restrict__ out)
{
    extern __shared__ float sm[];
    float* Wc1    = sm;                  // 16384 (K=1024)
    float* Wc0    = Wc1 + 16384;         // 10240 (K=640)
    float* A_s    = Wc0 + 10240;         // 2*8192 = 16384
    float* red    = A_s + 16384;         // 192*36 = 6912
    float* wlin_s = red + 6912;          // 512
    float* bias0  = wlin_s + 512;        // 16
    float* bias1  = bias0 + 16;          // 16

    const int tid = threadIdx.x;
    const int u0  = blockIdx.x * 4;

    __shared__ unsigned s_base;
    if (tid == 0) s_base = atomicAdd(&g_release, 0u);

    // zero initial states + decoder feedback input
    {
        int g = blockIdx.x * NTH + tid;
        for (int i = g; i < HH * BB; i += GRIDX * NTH) { g_h0T[0][i] = 0.0f; g_h1T[0][i] = 0.0f; }
        for (int i = g; i < II * BB; i += GRIDX * NTH) g_decT[i] = 0.0f;
    }

    load_layer_weights(Wc0, bias0, II, Wih_en0, Whh_en0, bih_en0, bhh_en0, u0);
    load_layer_weights(Wc1, bias1, HH, Wih_en1, Whh_en1, bih_en1, bhh_en1, u0);
    __syncthreads();

    unsigned base = s_base;
    unsigned nsync = 0;
    grid_sync(base, ++nsync);

    float c0[8] = {0,0,0,0,0,0,0,0};
    float c1[8] = {0,0,0,0,0,0,0,0};

    int p = 0;
    // ---- encoder ----
    for (int t = 0; t < SS; t++) {
        lstm_step(g_xT + (size_t)t * II * BB, 2, g_h0T[p], 8,
                  Wc0, bias0, A_s, red, g_h0T[p ^ 1] + u0 * BB, c0);
        grid_sync(base, ++nsync);
        lstm_step(g_h0T[p ^ 1], 8, g_h1T[p], 8,
                  Wc1, bias1, A_s, red, g_h1T[p ^ 1] + u0 * BB, c1);
        grid_sync(base, ++nsync);
        p ^= 1;
    }

    // ---- swap to decoder weights ----
    load_layer_weights(Wc0, bias0, II, Wih_de0, Whh_de0, bih_de0, bhh_de0, u0);
    load_layer_weights(Wc1, bias1, HH, Wih_de1, Whh_de1, bih_de1, bhh_de1, u0);
    for (int idx = tid; idx < HH; idx += NTH) wlin_s[idx] = Wlin[blockIdx.x * HH + idx];
    __syncthreads();

    // ---- decoder (closed loop) ----
    for (int t = 0; t < SS; t++) {
        lstm_step(g_decT, 2, g_h0T[p], 8,
                  Wc0, bias0, A_s, red, g_h0T[p ^ 1] + u0 * BB, c0);
        grid_sync(base, ++nsync);
        lstm_step(g_h0T[p ^ 1], 8, g_h1T[p], 8,
                  Wc1, bias1, A_s, red, g_h1T[p ^ 1] + u0 * BB, c1);
        grid_sync(base, ++nsync);
        pred_step(g_h1T[p ^ 1], wlin_s, A_s, red, t, out, blockIdx.x);
        grid_sync(base, ++nsync);
        p ^= 1;
    }
}

extern "C" void kernel_launch(void* const* d_in, const int* in_sizes, int n_in,
                              void* d_out, int out_size)
{
    const float* p[18];
    for (int i = 0; i < 18; i++) p[i] = (const float*)d_in[i];

    transpose_x<<<dim3(SS, II / 32, BB / 32), dim3(32, 8)>>>(p[0]);

    const size_t shmem = (16384 + 10240 + 16384 + 6912 + 512 + 16 + 16) * sizeof(float); // 201856 B
    cudaFuncSetAttribute(lstm_ae_kernel, cudaFuncAttributeMaxDynamicSharedMemorySize, (int)shmem);

    lstm_ae_kernel<<<GRIDX, NTH, shmem>>>(
        p[1], p[2], p[3], p[4],
        p[5], p[6], p[7], p[8],
        p[9], p[10], p[11], p[12],
        p[13], p[14], p[15], p[16],
        p[17],
        (float*)d_out);
}

// round 9
// speedup vs baseline: 1.3886x; 1.0918x over previous
#include <cuda_runtime.h>
#include <cstdint>

#define GRIDX 128
#define NTH   256
#define BB    128
#define SS    512
#define II    128
#define HH    512

// ---------------- persistent device state (no allocations allowed) -------------
static __device__ __align__(16) float g_xT[(size_t)SS*II*BB];   // [t][i][b]
static __device__ __align__(16) float g_h0T[2][HH*BB];          // [u][b]
static __device__ __align__(16) float g_h1T[2][HH*BB];
static __device__ __align__(16) float g_decT[II*BB];            // [i][b]
static __device__ unsigned g_arrive = 0;
static __device__ unsigned g_release = 0;

__device__ __forceinline__ float sigf(float x){ return 1.0f/(1.0f+__expf(-x)); }
__device__ __forceinline__ float tanhf_(float x){ return 1.0f - 2.0f/(__expf(2.0f*x)+1.0f); }

// ---- packed f32x2 (dual-rate fp32; proven in R3) ----
typedef unsigned long long ull;
#define PACK2(d,lo,hi) asm("mov.b64 %0,{%1,%2};" : "=l"(d) : "f"(lo),"f"(hi))
#define FMA2(d,a,b)    asm("fma.rn.f32x2 %0,%1,%2,%0;" : "+l"(d) : "l"(a),"l"(b))

// software grid barrier: 128 co-resident CTAs (1 CTA/SM via 170KB smem)
__device__ __forceinline__ void grid_sync(unsigned base, unsigned target)
{
    __syncthreads();
    if (threadIdx.x == 0) {
        __threadfence();
        unsigned arrived = atomicAdd(&g_arrive, 1u);
        if (arrived == GRIDX - 1u) {
            g_arrive = 0u;
            __threadfence();
            atomicAdd(&g_release, 1u);
        } else {
            volatile unsigned* rel = &g_release;
            while ((*rel - base) < target) { __nanosleep(32); }
        }
        __threadfence();
    }
    __syncthreads();
}

// Weights -> SMEM as Wc[k][16]; col c = unit*4+gate, global row R = gate*H+u0+unit.
__device__ void load_layer_weights(float* Wc, float* bias, int lenA,
                                   const float* __restrict__ W_ih,
                                   const float* __restrict__ W_hh,
                                   const float* __restrict__ b_ih,
                                   const float* __restrict__ b_hh, int u0)
{
    const int tid = threadIdx.x;
    const int K = lenA + HH;
    for (int idx = tid; idx < K * 16; idx += NTH) {
        int k  = idx >> 4;
        int c  = idx & 15;
        int j  = c >> 2;
        int gt = c & 3;
        int R  = gt * HH + u0 + j;
        Wc[idx] = (k < lenA) ? W_ih[R * lenA + k] : W_hh[R * HH + (k - lenA)];
    }
    if (tid < 16) {
        int j = tid >> 2, gt = tid & 3;
        int R = gt * HH + u0 + j;
        bias[tid] = b_ih[R] + b_hh[R];
    }
}

// One LSTM layer step for this CTA's 4 units over 128 batches.
// acts = concat(srcA [k 0..lenA), srcB [k lenA..K)), rows [k][128b] fp32, gmem-direct.
// warp w handles k-slice [w*K/8, (w+1)*K/8); lane: bg = l>>1 (8 batches), gg = l&1 (8 cols).
__device__ void lstm_step(const float* __restrict__ srcA, int lenA,
                          const float* __restrict__ srcB,
                          const float* __restrict__ Wc, const float* __restrict__ bias_s,
                          ull* __restrict__ red,
                          float* __restrict__ hOut, float* c_st, int ub)
{
    const int tid = threadIdx.x;
    const int w = tid >> 5, l = tid & 31;
    const int bg = l >> 1, gg = l & 1;
    const int K = lenA + HH;
    const int kper = K >> 3;
    const int k0 = w * kper, k1 = k0 + kper;

    ull acc[4][8];
#pragma unroll
    for (int bp = 0; bp < 4; bp++)
#pragma unroll
        for (int cp = 0; cp < 8; cp++) { float z = 0.0f; PACK2(acc[bp][cp], z, z); }

#define KBODY(ROWPTR, KK)                                                        \
    do {                                                                         \
        const ulonglong2* ap = (const ulonglong2*)((ROWPTR) + bg * 8);           \
        ulonglong2 A0 = ap[0], A1 = ap[1];                                       \
        const float4* wp = (const float4*)(Wc + (KK) * 16 + gg * 8);             \
        float4 wa = wp[0], wb = wp[1];                                           \
        ull w0,w1,w2,w3,w4,w5,w6,w7;                                             \
        PACK2(w0, wa.x, wa.x); PACK2(w1, wa.y, wa.y);                            \
        PACK2(w2, wa.z, wa.z); PACK2(w3, wa.w, wa.w);                            \
        PACK2(w4, wb.x, wb.x); PACK2(w5, wb.y, wb.y);                            \
        PACK2(w6, wb.z, wb.z); PACK2(w7, wb.w, wb.w);                            \
        FMA2(acc[0][0], A0.x, w0); FMA2(acc[0][1], A0.x, w1);                    \
        FMA2(acc[0][2], A0.x, w2); FMA2(acc[0][3], A0.x, w3);                    \
        FMA2(acc[0][4], A0.x, w4); FMA2(acc[0][5], A0.x, w5);                    \
        FMA2(acc[0][6], A0.x, w6); FMA2(acc[0][7], A0.x, w7);                    \
        FMA2(acc[1][0], A0.y, w0); FMA2(acc[1][1], A0.y, w1);                    \
        FMA2(acc[1][2], A0.y, w2); FMA2(acc[1][3], A0.y, w3);                    \
        FMA2(acc[1][4], A0.y, w4); FMA2(acc[1][5], A0.y, w5);                    \
        FMA2(acc[1][6], A0.y, w6); FMA2(acc[1][7], A0.y, w7);                    \
        FMA2(acc[2][0], A1.x, w0); FMA2(acc[2][1], A1.x, w1);                    \
        FMA2(acc[2][2], A1.x, w2); FMA2(acc[2][3], A1.x, w3);                    \
        FMA2(acc[2][4], A1.x, w4); FMA2(acc[2][5], A1.x, w5);                    \
        FMA2(acc[2][6], A1.x, w6); FMA2(acc[2][7], A1.x, w7);                    \
        FMA2(acc[3][0], A1.y, w0); FMA2(acc[3][1], A1.y, w1);                    \
        FMA2(acc[3][2], A1.y, w2); FMA2(acc[3][3], A1.y, w3);                    \
        FMA2(acc[3][4], A1.y, w4); FMA2(acc[3][5], A1.y, w5);                    \
        FMA2(acc[3][6], A1.y, w6); FMA2(acc[3][7], A1.y, w7);                    \
    } while (0)

    {   // segment A
        int s0 = (k0 > 0) ? k0 : 0;
        int s1 = (k1 < lenA) ? k1 : lenA;
#pragma unroll 2
        for (int k = s0; k < s1; k++) KBODY(srcA + (size_t)k * BB, k);
    }
    {   // segment B
        int s0 = (k0 > lenA) ? k0 : lenA;
        int s1 = k1;
#pragma unroll 2
        for (int k = s0; k < s1; k++) KBODY(srcB + (size_t)(k - lenA) * BB, k);
    }
#undef KBODY

    // split-K-8 reduction through SMEM: red[w][lane][bp*8+cp] (ull)
    {
        ull* rp = red + ((size_t)(w * 32 + l) << 5);
#pragma unroll
        for (int bp = 0; bp < 4; bp++)
#pragma unroll
            for (int cp = 0; cp < 8; cp++)
                rp[bp * 8 + cp] = acc[bp][cp];
    }
    __syncthreads();

    // gather + cell update: thread t handles (b = t&127, ul = (t>>7)*2 + j), j=0,1
    const float* redf = (const float*)red;
    const int b = tid & 127;
    const int ulbase = (tid >> 7) * 2;
#pragma unroll
    for (int j = 0; j < 2; j++) {
        const int ul = ulbase + j;
        float g4[4];
#pragma unroll
        for (int gt = 0; gt < 4; gt++) {
            const int c = ul * 4 + gt;
            const int lane = (b >> 3) * 2 + (c >> 3);
            const int cp = c & 7, bp = (b & 7) >> 1, half = b & 1;
            float s = bias_s[c];
#pragma unroll
            for (int w2 = 0; w2 < 8; w2++)
                s += redf[((((w2 * 32 + lane) << 5) + bp * 8 + cp) << 1) + half];
            g4[gt] = s;
        }
        float cn = sigf(g4[1]) * c_st[j] + sigf(g4[0]) * tanhf_(g4[2]);
        c_st[j] = cn;
        hOut[(size_t)(ub + ul) * BB + b] = sigf(g4[3]) * tanhf_(cn);
    }
    __syncthreads();
}

// pred[b, icol] = h1[b,:] . wlin  (h1 stored transposed [u][b]); gmem-direct
__device__ void pred_step(const float* __restrict__ h1T, const float* __restrict__ wlin_s,
                          float* __restrict__ redf,
                          int t, float* __restrict__ out, int icol)
{
    const int tid = threadIdx.x;
    const int b = tid >> 1, half = tid & 1;
    const float* hp = h1T + (size_t)(half * 256) * BB + b;
    const float* wl = wlin_s + half * 256;
    float acc = 0.0f;
#pragma unroll 8
    for (int u = 0; u < 256; u++)
        acc += hp[(size_t)u * BB] * wl[u];
    __syncthreads();
    if (half) redf[b] = acc;
    __syncthreads();
    if (!half) {
        float p = acc + redf[b];
        out[((size_t)b * SS + t) * II + icol] = p;
        g_decT[icol * BB + b] = p;
    }
    __syncthreads();
}

// x[b][t][i] -> xT[t][i][b]
__global__ void transpose_x(const float* __restrict__ x)
{
    __shared__ float tile[32][33];
    int t = blockIdx.x;
    int i0 = blockIdx.y * 32, b0 = blockIdx.z * 32;
    int tx = threadIdx.x, ty = threadIdx.y;
#pragma unroll
    for (int j = 0; j < 32; j += 8)
        tile[ty + j][tx] = x[((size_t)(b0 + ty + j) * SS + t) * II + i0 + tx];
    __syncthreads();
#pragma unroll
    for (int j = 0; j < 32; j += 8)
        g_xT[((size_t)t * II + i0 + ty + j) * BB + b0 + tx] = tile[tx][ty + j];
}

__global__ void __launch_bounds__(NTH, 1)
lstm_ae_kernel(const float* Wih_en0, const float* Whh_en0, const float* bih_en0, const float* bhh_en0,
               const float* Wih_en1, const float* Whh_en1, const float* bih_en1, const float* bhh_en1,
               const float* Wih_de0, const float* Whh_de0, const float* bih_de0, const float* bhh_de0,
               const float* Wih_de1, const float* Whh_de1, const float* bih_de1, const float* bhh_de1,
               const float* Wlin,
               float* __restrict__ out)
{
    extern __shared__ float sm[];
    float* Wc1    = sm;                  // 16384 f32 (K=1024 layer)
    float* Wc0    = Wc1 + 16384;         // 10240 f32 (K=640 layer)
    ull*   red    = (ull*)(Wc0 + 10240); // 8192 ull = 16384 f32 slots
    float* wlin_s = (float*)(red + 8192);// 512
    float* bias0  = wlin_s + 512;        // 16
    float* bias1  = bias0 + 16;          // 16

    const int tid = threadIdx.x;
    const int u0  = blockIdx.x * 4;

    __shared__ unsigned s_base;
    if (tid == 0) s_base = atomicAdd(&g_release, 0u);

    // zero initial states + decoder feedback
    {
        int g = blockIdx.x * NTH + tid;
        for (int i = g; i < HH * BB; i += GRIDX * NTH) { g_h0T[0][i] = 0.0f; g_h1T[0][i] = 0.0f; }
        for (int i = g; i < II * BB; i += GRIDX * NTH) g_decT[i] = 0.0f;
    }

    load_layer_weights(Wc0, bias0, II, Wih_en0, Whh_en0, bih_en0, bhh_en0, u0);
    load_layer_weights(Wc1, bias1, HH, Wih_en1, Whh_en1, bih_en1, bhh_en1, u0);
    __syncthreads();

    unsigned base = s_base;
    unsigned nsync = 0;
    grid_sync(base, ++nsync);

    float c0[2] = {0.f, 0.f};
    float c1[2] = {0.f, 0.f};

    int p = 0;
    // ---- encoder ----
    for (int t = 0; t < SS; t++) {
        lstm_step(g_xT + (size_t)t * II * BB, II, g_h0T[p],
                  Wc0, bias0, red, g_h0T[p ^ 1], c0, u0);
        grid_sync(base, ++nsync);
        lstm_step(g_h0T[p ^ 1], HH, g_h1T[p],
                  Wc1, bias1, red, g_h1T[p ^ 1], c1, u0);
        grid_sync(base, ++nsync);
        p ^= 1;
    }

    // ---- swap to decoder weights ----
    load_layer_weights(Wc0, bias0, II, Wih_de0, Whh_de0, bih_de0, bhh_de0, u0);
    load_layer_weights(Wc1, bias1, HH, Wih_de1, Whh_de1, bih_de1, bhh_de1, u0);
    for (int k = tid; k < HH; k += NTH) wlin_s[k] = Wlin[blockIdx.x * HH + k];
    __syncthreads();

    // ---- decoder (closed loop) ----
    for (int t = 0; t < SS; t++) {
        lstm_step(g_decT, II, g_h0T[p],
                  Wc0, bias0, red, g_h0T[p ^ 1], c0, u0);
        grid_sync(base, ++nsync);
        lstm_step(g_h0T[p ^ 1], HH, g_h1T[p],
                  Wc1, bias1, red, g_h1T[p ^ 1], c1, u0);
        grid_sync(base, ++nsync);
        pred_step(g_h1T[p ^ 1], wlin_s, (float*)red, t, out, blockIdx.x);
        grid_sync(base, ++nsync);
        p ^= 1;
    }
}

extern "C" void kernel_launch(void* const* d_in, const int* in_sizes, int n_in,
                              void* d_out, int out_size)
{
    const float* p[18];
    for (int i = 0; i < 18; i++) p[i] = (const float*)d_in[i];

    transpose_x<<<dim3(SS, II / 32, BB / 32), dim3(32, 8)>>>(p[0]);

    const size_t shmem = (16384 + 10240 + 16384 + 512 + 16 + 16) * sizeof(float); // 174208 B
    cudaFuncSetAttribute(lstm_ae_kernel, cudaFuncAttributeMaxDynamicSharedMemorySize, (int)shmem);

    lstm_ae_kernel<<<GRIDX, NTH, shmem>>>(
        p[1], p[2], p[3], p[4],
        p[5], p[6], p[7], p[8],
        p[9], p[10], p[11], p[12],
        p[13], p[14], p[15], p[16],
        p[17],
        (float*)d_out);
}